// round 2
// baseline (speedup 1.0000x reference)
#include <cuda_runtime.h>
#include <cuda_bf16.h>
#include <math.h>

// ---------------- problem constants ----------------
#define Bn      2
#define Cn      256
#define Hn      256
#define Wn      256
#define HEADS   4
#define CH      64          // C / HEADS
#define WSZ     8
#define NH      32          // H / WSZ
#define NWIN    1024        // NH*NH per batch
#define WINSZ   64          // WSZ*WSZ
#define NWF     307         // int(1024*0.3)
#define NSEL    614         // B * NWF
#define SRn     8
#define H1      32
#define HW1     1024
#define NTOK    (NSEL*WINSZ)   // 39296
#define GTOK    (Bn*HW1)       // 2048
#define SCALE   0.125f         // CH^-0.5

// ---------------- scratch (no runtime allocation allowed) ----------------
__device__ float d_wf[NTOK * Cn];        // 40.2 MB  token buffer (wf, residuals accumulate here)
__device__ float d_q [NTOK * Cn];        // 40.2 MB  Q buffer (reused for proj output)
__device__ float d_kv[NTOK * 2 * Cn];    // 80.5 MB  KV buffer (local KV, reused for global KV)
__device__ float d_g [GTOK * Cn];        //  2.1 MB  global-branch tokens
__device__ int   d_sel[NSEL];            // selected window indices (per-batch local index)

// ============================================================
// 1) window scores + top-k selection (rank by count)
//    one block per batch, 1024 threads = one per window
// ============================================================
__global__ void select_kernel(const float* __restrict__ unc, int* __restrict__ sel) {
    __shared__ float sc[NWIN];
    int b  = blockIdx.x;
    int wi = threadIdx.x;
    int wh = wi >> 5, ww = wi & 31;
    const float* u = unc + ((size_t)b * Hn + wh * WSZ) * Wn + ww * WSZ;
    float s = 0.f;
    #pragma unroll
    for (int i = 0; i < WSZ; i++)
        #pragma unroll
        for (int j = 0; j < WSZ; j++)
            s += u[i * Wn + j];
    sc[wi] = s;
    __syncthreads();
    int rank = 0;
    for (int j = 0; j < NWIN; j++) {
        float sj = sc[j];
        rank += (sj > s) || (sj == s && j < wi);
    }
    if (rank < NWF) sel[b * NWF + rank] = wi;
}

// ============================================================
// 2) gather selected windows -> wf [NTOK, C] (token-major)
// ============================================================
__global__ void gather_kernel(const float* __restrict__ feat, const int* __restrict__ sel,
                              float* __restrict__ wf) {
    int n = blockIdx.x;          // 0..613
    int c = threadIdx.x;         // 0..255
    int b = n / NWF;
    int wi = sel[n];
    int wh = wi >> 5, ww = wi & 31;
    const float* src = feat + (((size_t)b * Cn + c) * Hn + wh * WSZ) * Wn + ww * WSZ;
    float* dst = wf + (size_t)n * WINSZ * Cn + c;
    #pragma unroll
    for (int p = 0; p < WINSZ; p++) {
        dst[p * Cn] = src[(p >> 3) * Wn + (p & 7)];
    }
}

// ============================================================
// 3) generic fp32 SGEMM  C[M,N] = A[M,K] @ B[K,N] (+bias)
//    64x64 tile, BK=16, 256 threads, 4x4 register tile
//    all dims are multiples of the tile in this problem
// ============================================================
__global__ void sgemm_kernel(const float* __restrict__ A, const float* __restrict__ Bm,
                             float* __restrict__ C, const float* __restrict__ bias,
                             int M, int N, int K) {
    __shared__ float As[16 * 64];
    __shared__ float Bs[16 * 64];
    int tid = threadIdx.x;
    int tx = tid & 15, ty = tid >> 4;
    int m0 = blockIdx.x << 6, n0 = blockIdx.y << 6;
    int arow = tid >> 2, akq = (tid & 3) << 2;   // A tile loader: row 0..63, k 0,4,8,12
    int brow = tid >> 4, bnq = (tid & 15) << 2;  // B tile loader: k 0..15, n 0..60

    float acc[4][4] = {};

    for (int k0 = 0; k0 < K; k0 += 16) {
        float4 av = *(const float4*)(A + (size_t)(m0 + arow) * K + k0 + akq);
        As[(akq + 0) * 64 + arow] = av.x;
        As[(akq + 1) * 64 + arow] = av.y;
        As[(akq + 2) * 64 + arow] = av.z;
        As[(akq + 3) * 64 + arow] = av.w;
        *(float4*)(Bs + brow * 64 + bnq) =
            *(const float4*)(Bm + (size_t)(k0 + brow) * N + n0 + bnq);
        __syncthreads();
        #pragma unroll
        for (int kk = 0; kk < 16; kk++) {
            float4 a4 = *(const float4*)(As + kk * 64 + ty * 4);
            float4 b4 = *(const float4*)(Bs + kk * 64 + tx * 4);
            float a[4] = {a4.x, a4.y, a4.z, a4.w};
            float b[4] = {b4.x, b4.y, b4.z, b4.w};
            #pragma unroll
            for (int i = 0; i < 4; i++)
                #pragma unroll
                for (int j = 0; j < 4; j++)
                    acc[i][j] += a[i] * b[j];
        }
        __syncthreads();
    }

    #pragma unroll
    for (int i = 0; i < 4; i++) {
        #pragma unroll
        for (int j = 0; j < 4; j++) {
            float v = acc[i][j];
            if (bias) v += __ldg(&bias[n0 + tx * 4 + j]);
            C[(size_t)(m0 + ty * 4 + i) * N + n0 + tx * 4 + j] = v;
        }
    }
}

// ============================================================
// 4) fused attention block (local & global via gmode)
//    block = (window n, head h), 256 threads
//    64 queries per block, keys streamed in chunks of 64 with
//    online (flash) softmax; output accumulated into wf (+=)
// ============================================================
#define ATT_SMEM_FLOATS (64*64 + 3*(64*65) + 3*64)

__global__ void attn_kernel(const float* __restrict__ Q, const float* __restrict__ KV,
                            float* __restrict__ wfacc, int ktokens, int gmode) {
    extern __shared__ float sm[];
    float* Qs    = sm;                // [64][64]
    float* Ks    = Qs + 64 * 64;      // [64][65]
    float* Vs    = Ks + 64 * 65;      // [64][65]
    float* Ss    = Vs + 64 * 65;      // [64][65]
    float* rowm  = Ss + 64 * 65;      // [64]
    float* rowl  = rowm + 64;         // [64]
    float* rowsc = rowl + 64;         // [64]

    int n = blockIdx.x, h = blockIdx.y;
    int tid = threadIdx.x;
    int qtok0 = n * WINSZ;
    int kbase = gmode ? (n / NWF) * HW1 : n * WINSZ;

    // load Q tile
    for (int idx = tid; idx < 64 * 64; idx += 256) {
        int p = idx >> 6, c = idx & 63;
        Qs[idx] = Q[(size_t)(qtok0 + p) * Cn + h * CH + c];
    }
    if (tid < 64) { rowm[tid] = -1e30f; rowl[tid] = 0.f; }

    int rg = tid >> 4, cg = tid & 15;
    int r0 = rg * 4, c0 = cg * 4;
    float acc[4][4] = {};

    int nchunks = ktokens >> 6;
    for (int chk = 0; chk < nchunks; chk++) {
        __syncthreads();   // Q/rowm ready (iter0); Ks/Vs/Ss free (iter>0)
        for (int idx = tid; idx < 64 * 64; idx += 256) {
            int j = idx >> 6, c = idx & 63;
            size_t base = (size_t)(kbase + chk * 64 + j) * (2 * Cn) + h * CH + c;
            Ks[j * 65 + c] = KV[base];
            Vs[j * 65 + c] = KV[base + Cn];
        }
        __syncthreads();

        // S = Q K^T * scale  (4x4 per thread)
        float s[4][4] = {};
        #pragma unroll 8
        for (int kk = 0; kk < 64; kk++) {
            float qv[4], kv[4];
            #pragma unroll
            for (int i = 0; i < 4; i++) qv[i] = Qs[(r0 + i) * 64 + kk];
            #pragma unroll
            for (int j = 0; j < 4; j++) kv[j] = Ks[(c0 + j) * 65 + kk];
            #pragma unroll
            for (int i = 0; i < 4; i++)
                #pragma unroll
                for (int j = 0; j < 4; j++)
                    s[i][j] += qv[i] * kv[j];
        }
        #pragma unroll
        for (int i = 0; i < 4; i++)
            #pragma unroll
            for (int j = 0; j < 4; j++)
                Ss[(r0 + i) * 65 + c0 + j] = s[i][j] * SCALE;
        __syncthreads();

        // online softmax (one thread per row)
        if (tid < 64) {
            float m = rowm[tid];
            float* row = Ss + tid * 65;
            float cm = -1e30f;
            #pragma unroll 8
            for (int j = 0; j < 64; j++) cm = fmaxf(cm, row[j]);
            float nm = fmaxf(m, cm);
            float scl = expf(m - nm);
            float ssum = 0.f;
            #pragma unroll 8
            for (int j = 0; j < 64; j++) {
                float e = expf(row[j] - nm);
                row[j] = e;
                ssum += e;
            }
            rowm[tid] = nm;
            rowsc[tid] = scl;
            rowl[tid] = rowl[tid] * scl + ssum;
        }
        __syncthreads();

        // O = O*rowscale + P @ V
        float rsc[4];
        #pragma unroll
        for (int i = 0; i < 4; i++) rsc[i] = rowsc[r0 + i];
        #pragma unroll
        for (int i = 0; i < 4; i++)
            #pragma unroll
            for (int j = 0; j < 4; j++)
                acc[i][j] *= rsc[i];
        #pragma unroll 8
        for (int jj = 0; jj < 64; jj++) {
            float pv[4], vv[4];
            #pragma unroll
            for (int i = 0; i < 4; i++) pv[i] = Ss[(r0 + i) * 65 + jj];
            #pragma unroll
            for (int j = 0; j < 4; j++) vv[j] = Vs[jj * 65 + c0 + j];
            #pragma unroll
            for (int i = 0; i < 4; i++)
                #pragma unroll
                for (int j = 0; j < 4; j++)
                    acc[i][j] += pv[i] * vv[j];
        }
    }

    // normalize and accumulate residual into wf
    float rl[4];
    #pragma unroll
    for (int i = 0; i < 4; i++) rl[i] = 1.f / rowl[r0 + i];
    #pragma unroll
    for (int i = 0; i < 4; i++)
        #pragma unroll
        for (int j = 0; j < 4; j++)
            wfacc[(size_t)(qtok0 + r0 + i) * Cn + h * CH + c0 + j] += acc[i][j] * rl[i];
}

// ============================================================
// 5) global branch: depthwise 8x8/s8 conv -> LN(C) -> exact GELU
//    one block per (b, token), thread = channel
// ============================================================
__global__ void convlngelu_kernel(const float* __restrict__ feat,
                                  const float* __restrict__ sr_w,
                                  const float* __restrict__ sr_b,
                                  const float* __restrict__ ln_g,
                                  const float* __restrict__ ln_b,
                                  float* __restrict__ g) {
    __shared__ float red[Cn];
    int bt = blockIdx.x;
    int b = bt >> 10, t = bt & 1023;
    int y1 = t >> 5, x1 = t & 31;
    int c = threadIdx.x;

    const float* src = feat + (((size_t)b * Cn + c) * Hn + y1 * SRn) * Wn + x1 * SRn;
    const float* w = sr_w + c * (SRn * SRn);
    float acc = sr_b[c];
    #pragma unroll
    for (int i = 0; i < SRn; i++)
        #pragma unroll
        for (int j = 0; j < SRn; j++)
            acc += src[i * Wn + j] * w[i * SRn + j];

    // mean
    red[c] = acc;
    __syncthreads();
    for (int off = 128; off > 0; off >>= 1) {
        if (c < off) red[c] += red[c + off];
        __syncthreads();
    }
    float mu = red[0] * (1.f / Cn);
    __syncthreads();
    // variance
    float dv = acc - mu;
    red[c] = dv * dv;
    __syncthreads();
    for (int off = 128; off > 0; off >>= 1) {
        if (c < off) red[c] += red[c + off];
        __syncthreads();
    }
    float var = red[0] * (1.f / Cn);
    float rs = rsqrtf(var + 1e-5f);
    float xh = dv * rs * ln_g[c] + ln_b[c];
    float gl = 0.5f * xh * (1.f + erff(xh * 0.70710678118654752440f));
    g[(size_t)bt * Cn + c] = gl;
}

// ============================================================
// 6) scatter-add projected windows back into out (out = feat copy)
// ============================================================
__global__ void scatter_kernel(const float* __restrict__ P, const int* __restrict__ sel,
                               float* __restrict__ out) {
    int n = blockIdx.x;
    int c = threadIdx.x;
    int b = n / NWF;
    int wi = sel[n];
    int wh = wi >> 5, ww = wi & 31;
    const float* src = P + (size_t)n * WINSZ * Cn + c;
    float* dst = out + (((size_t)b * Cn + c) * Hn + wh * WSZ) * Wn + ww * WSZ;
    #pragma unroll
    for (int p = 0; p < WINSZ; p++) {
        dst[(p >> 3) * Wn + (p & 7)] += src[p * Cn];
    }
}

// ============================================================
// launch
// ============================================================
extern "C" void kernel_launch(void* const* d_in, const int* in_sizes, int n_in,
                              void* d_out, int out_size) {
    const float* feat  = (const float*)d_in[0];
    const float* unc   = (const float*)d_in[1];
    const float* sr_w  = (const float*)d_in[2];
    const float* sr_b  = (const float*)d_in[3];
    const float* ln_g  = (const float*)d_in[4];
    const float* ln_b  = (const float*)d_in[5];
    const float* wq_l  = (const float*)d_in[6];
    const float* wkv_l = (const float*)d_in[7];
    const float* wq_g  = (const float*)d_in[8];
    const float* wkv_g = (const float*)d_in[9];
    const float* wp    = (const float*)d_in[10];
    const float* bp    = (const float*)d_in[11];
    float* out = (float*)d_out;

    float *wf, *q, *kv, *g;
    int* sel;
    cudaGetSymbolAddress((void**)&wf,  d_wf);
    cudaGetSymbolAddress((void**)&q,   d_q);
    cudaGetSymbolAddress((void**)&kv,  d_kv);
    cudaGetSymbolAddress((void**)&g,   d_g);
    cudaGetSymbolAddress((void**)&sel, d_sel);

    size_t att_smem = ATT_SMEM_FLOATS * sizeof(float);
    cudaFuncSetAttribute(attn_kernel, cudaFuncAttributeMaxDynamicSharedMemorySize,
                         (int)att_smem);

    // out = feature_map (identity part of the scatter-add)
    cudaMemcpyAsync(out, feat, (size_t)Bn * Cn * Hn * Wn * sizeof(float),
                    cudaMemcpyDeviceToDevice);

    // top-k window selection + gather
    select_kernel<<<Bn, NWIN>>>(unc, sel);
    gather_kernel<<<NSEL, Cn>>>(feat, sel, wf);

    // local branch: Q/KV projections + windowed MHSA (residual into wf)
    sgemm_kernel<<<dim3(NTOK / 64, Cn / 64), 256>>>(wf, wq_l, q, nullptr, NTOK, Cn, Cn);
    sgemm_kernel<<<dim3(NTOK / 64, 2 * Cn / 64), 256>>>(wf, wkv_l, kv, nullptr, NTOK, 2 * Cn, Cn);
    attn_kernel<<<dim3(NSEL, HEADS), 256, att_smem>>>(q, kv, wf, WINSZ, 0);

    // global branch tokens + KV projection
    convlngelu_kernel<<<GTOK, Cn>>>(feat, sr_w, sr_b, ln_g, ln_b, g);
    sgemm_kernel<<<dim3(GTOK / 64, 2 * Cn / 64), 256>>>(g, wkv_g, kv, nullptr, GTOK, 2 * Cn, Cn);

    // cross-attention (queries = updated wf), residual into wf
    sgemm_kernel<<<dim3(NTOK / 64, Cn / 64), 256>>>(wf, wq_g, q, nullptr, NTOK, Cn, Cn);
    attn_kernel<<<dim3(NSEL, HEADS), 256, att_smem>>>(q, kv, wf, HW1, 1);

    // final projection + bias, scatter-add into out
    sgemm_kernel<<<dim3(NTOK / 64, Cn / 64), 256>>>(wf, wp, q, bp, NTOK, Cn, Cn);
    scatter_kernel<<<NSEL, Cn>>>(q, sel, out);
}

// round 3
// speedup vs baseline: 1.0328x; 1.0328x over previous
#include <cuda_runtime.h>
#include <cuda_bf16.h>
#include <math.h>

// ---------------- problem constants ----------------
#define Bn      2
#define Cn      256
#define Hn      256
#define Wn      256
#define HEADS   4
#define CH      64
#define WSZ     8
#define NH      32
#define NWIN    1024
#define WINSZ   64
#define NWF     307
#define NSEL    614
#define SRn     8
#define H1      32
#define HW1     1024
#define NTOK    (NSEL*WINSZ)   // 39296
#define GTOK    (Bn*HW1)       // 2048
#define SCALE   0.125f

// ---------------- scratch ----------------
__device__ float d_wf[NTOK * Cn];
__device__ float d_q [NTOK * Cn];
__device__ float d_kv[NTOK * 2 * Cn];
__device__ float d_g [GTOK * Cn];
__device__ int   d_sel[NSEL];

// ============================================================
// 1) window scores + top-k selection (rank by count)
// ============================================================
__global__ void select_kernel(const float* __restrict__ unc, int* __restrict__ sel) {
    __shared__ float sc[NWIN];
    int b  = blockIdx.x;
    int wi = threadIdx.x;
    int wh = wi >> 5, ww = wi & 31;
    const float* u = unc + ((size_t)b * Hn + wh * WSZ) * Wn + ww * WSZ;
    float s = 0.f;
    #pragma unroll
    for (int i = 0; i < WSZ; i++)
        #pragma unroll
        for (int j = 0; j < WSZ; j++)
            s += u[i * Wn + j];
    sc[wi] = s;
    __syncthreads();
    int rank = 0;
    for (int j = 0; j < NWIN; j++) {
        float sj = sc[j];
        rank += (sj > s) || (sj == s && j < wi);
    }
    if (rank < NWF) sel[b * NWF + rank] = wi;
}

// ============================================================
// 2) gather selected windows -> wf [NTOK, C]
// ============================================================
__global__ void gather_kernel(const float* __restrict__ feat, const int* __restrict__ sel,
                              float* __restrict__ wf) {
    int n = blockIdx.x;
    int c = threadIdx.x;
    int b = n / NWF;
    int wi = sel[n];
    int wh = wi >> 5, ww = wi & 31;
    const float* src = feat + (((size_t)b * Cn + c) * Hn + wh * WSZ) * Wn + ww * WSZ;
    float* dst = wf + (size_t)n * WINSZ * Cn + c;
    #pragma unroll
    for (int p = 0; p < WINSZ; p++) {
        dst[p * Cn] = src[(p >> 3) * Wn + (p & 7)];
    }
}

// ============================================================
// 3) fp32 SGEMM  C[M,N] = A[M,K] @ B[K,N] (+bias)
//    128x128 tile, BK=16, 256 threads, 8x8 register tile
// ============================================================
__global__ __launch_bounds__(256, 2)
void sgemm_kernel(const float* __restrict__ A, const float* __restrict__ Bm,
                  float* __restrict__ C, const float* __restrict__ bias,
                  int M, int N, int K) {
    __shared__ float As[16][132];   // transposed A tile [k][m], padded
    __shared__ float Bs[16][128];   // B tile [k][n]
    int tid = threadIdx.x;
    int tx = tid & 15, ty = tid >> 4;
    int m0 = blockIdx.x << 7, n0 = blockIdx.y << 7;

    int ar = tid >> 2;              // 0..63
    int ak = (tid & 3) << 2;        // 0,4,8,12
    int br = tid >> 5;              // 0..7
    int bn = (tid & 31) << 2;       // 0..124

    float acc[8][8] = {};
    float af[8], bf[8];

    const float* Aptr = A + (size_t)m0 * K;
    const float* Bptr = Bm + n0;

    for (int k0 = 0; k0 < K; k0 += 16) {
        #pragma unroll
        for (int u = 0; u < 2; u++) {
            int r = ar + u * 64;
            float4 v = *(const float4*)(Aptr + (size_t)r * K + k0 + ak);
            As[ak + 0][r] = v.x;
            As[ak + 1][r] = v.y;
            As[ak + 2][r] = v.z;
            As[ak + 3][r] = v.w;
        }
        #pragma unroll
        for (int u = 0; u < 2; u++) {
            int r = br + u * 8;
            *(float4*)(&Bs[r][bn]) = *(const float4*)(Bptr + (size_t)(k0 + r) * N + bn);
        }
        __syncthreads();
        #pragma unroll
        for (int kk = 0; kk < 16; kk++) {
            *(float4*)(af)     = *(const float4*)(&As[kk][ty * 8]);
            *(float4*)(af + 4) = *(const float4*)(&As[kk][ty * 8 + 4]);
            *(float4*)(bf)     = *(const float4*)(&Bs[kk][tx * 8]);
            *(float4*)(bf + 4) = *(const float4*)(&Bs[kk][tx * 8 + 4]);
            #pragma unroll
            for (int i = 0; i < 8; i++)
                #pragma unroll
                for (int j = 0; j < 8; j++)
                    acc[i][j] += af[i] * bf[j];
        }
        __syncthreads();
    }

    #pragma unroll
    for (int i = 0; i < 8; i++) {
        int row = m0 + ty * 8 + i;
        float* cp = C + (size_t)row * N + n0 + tx * 8;
        #pragma unroll
        for (int j = 0; j < 8; j++) {
            float v = acc[i][j];
            if (bias) v += __ldg(&bias[n0 + tx * 8 + j]);
            cp[j] = v;
        }
    }
}

// ============================================================
// 4) fused attention (flash-style), register softmax
//    block = (window n, head h), 256 threads, 4x4 tiles
//    rows of S map to 16 consecutive threads (half-warp) ->
//    shfl_xor butterfly reductions over lanes 0..15 / 16..31
// ============================================================
#define ATT_SMEM_FLOATS (64*64 + 3*(64*65))

__global__ __launch_bounds__(256)
void attn_kernel(const float* __restrict__ Q, const float* __restrict__ KV,
                 float* __restrict__ wfacc, int ktokens, int gmode) {
    extern __shared__ float sm[];
    float* Qs = sm;                // [64][64]  (scale pre-folded)
    float* Ks = Qs + 64 * 64;      // [64][65]  [key][ch]
    float* Vs = Ks + 64 * 65;      // [64][65]  [key][ch]
    float* Ss = Vs + 64 * 65;      // [64][65]  [row][key] (P values)

    int n = blockIdx.x, h = blockIdx.y;
    int tid = threadIdx.x;
    int qtok0 = n * WINSZ;
    int kbase = gmode ? (n / NWF) * HW1 : n * WINSZ;

    for (int idx = tid; idx < 64 * 64; idx += 256) {
        int p = idx >> 6, c = idx & 63;
        Qs[idx] = Q[(size_t)(qtok0 + p) * Cn + h * CH + c] * SCALE;
    }

    int rg = tid >> 4, cg = tid & 15;
    int r0 = rg * 4, c0 = cg * 4;
    float acc[4][4] = {};
    float rm[4] = {-1e30f, -1e30f, -1e30f, -1e30f};
    float rl[4] = {0.f, 0.f, 0.f, 0.f};

    int nchunks = ktokens >> 6;
    for (int chk = 0; chk < nchunks; chk++) {
        __syncthreads();
        for (int idx = tid; idx < 64 * 64; idx += 256) {
            int j = idx >> 6, c = idx & 63;
            size_t base = (size_t)(kbase + chk * 64 + j) * (2 * Cn) + h * CH + c;
            Ks[j * 65 + c] = KV[base];
            Vs[j * 65 + c] = KV[base + Cn];
        }
        __syncthreads();

        // S = (Q*scale) K^T
        float s[4][4] = {};
        #pragma unroll 8
        for (int kk = 0; kk < 64; kk++) {
            float qv[4], kv[4];
            #pragma unroll
            for (int i = 0; i < 4; i++) qv[i] = Qs[(r0 + i) * 64 + kk];
            #pragma unroll
            for (int j = 0; j < 4; j++) kv[j] = Ks[(c0 + j) * 65 + kk];
            #pragma unroll
            for (int i = 0; i < 4; i++)
                #pragma unroll
                for (int j = 0; j < 4; j++)
                    s[i][j] += qv[i] * kv[j];
        }

        // --- register softmax: butterfly over the 16-lane row group ---
        float mloc[4];
        #pragma unroll
        for (int i = 0; i < 4; i++)
            mloc[i] = fmaxf(fmaxf(s[i][0], s[i][1]), fmaxf(s[i][2], s[i][3]));
        #pragma unroll
        for (int off = 8; off >= 1; off >>= 1)
            #pragma unroll
            for (int i = 0; i < 4; i++)
                mloc[i] = fmaxf(mloc[i], __shfl_xor_sync(0xffffffffu, mloc[i], off));

        float lsum[4], scl[4];
        #pragma unroll
        for (int i = 0; i < 4; i++) {
            float nm = fmaxf(rm[i], mloc[i]);
            scl[i] = __expf(rm[i] - nm);
            float ls = 0.f;
            #pragma unroll
            for (int j = 0; j < 4; j++) {
                s[i][j] = __expf(s[i][j] - nm);
                ls += s[i][j];
            }
            lsum[i] = ls;
            rm[i] = nm;
        }
        #pragma unroll
        for (int off = 8; off >= 1; off >>= 1)
            #pragma unroll
            for (int i = 0; i < 4; i++)
                lsum[i] += __shfl_xor_sync(0xffffffffu, lsum[i], off);
        #pragma unroll
        for (int i = 0; i < 4; i++) {
            rl[i] = rl[i] * scl[i] + lsum[i];
            #pragma unroll
            for (int j = 0; j < 4; j++) {
                acc[i][j] *= scl[i];
                Ss[(r0 + i) * 65 + c0 + j] = s[i][j];
            }
        }
        __syncthreads();

        // O += P @ V
        #pragma unroll 8
        for (int jj = 0; jj < 64; jj++) {
            float pv[4], vv[4];
            #pragma unroll
            for (int i = 0; i < 4; i++) pv[i] = Ss[(r0 + i) * 65 + jj];
            #pragma unroll
            for (int j = 0; j < 4; j++) vv[j] = Vs[jj * 65 + c0 + j];
            #pragma unroll
            for (int i = 0; i < 4; i++)
                #pragma unroll
                for (int j = 0; j < 4; j++)
                    acc[i][j] += pv[i] * vv[j];
        }
    }

    #pragma unroll
    for (int i = 0; i < 4; i++) {
        float inv = 1.f / rl[i];
        #pragma unroll
        for (int j = 0; j < 4; j++)
            wfacc[(size_t)(qtok0 + r0 + i) * Cn + h * CH + c0 + j] += acc[i][j] * inv;
    }
}

// ============================================================
// 5) global branch: depthwise conv -> LN -> exact GELU
// ============================================================
__global__ void convlngelu_kernel(const float* __restrict__ feat,
                                  const float* __restrict__ sr_w,
                                  const float* __restrict__ sr_b,
                                  const float* __restrict__ ln_g,
                                  const float* __restrict__ ln_b,
                                  float* __restrict__ g) {
    __shared__ float red[Cn];
    int bt = blockIdx.x;
    int b = bt >> 10, t = bt & 1023;
    int y1 = t >> 5, x1 = t & 31;
    int c = threadIdx.x;

    const float* src = feat + (((size_t)b * Cn + c) * Hn + y1 * SRn) * Wn + x1 * SRn;
    const float* w = sr_w + c * (SRn * SRn);
    float acc = sr_b[c];
    #pragma unroll
    for (int i = 0; i < SRn; i++)
        #pragma unroll
        for (int j = 0; j < SRn; j++)
            acc += src[i * Wn + j] * w[i * SRn + j];

    red[c] = acc;
    __syncthreads();
    for (int off = 128; off > 0; off >>= 1) {
        if (c < off) red[c] += red[c + off];
        __syncthreads();
    }
    float mu = red[0] * (1.f / Cn);
    __syncthreads();
    float dv = acc - mu;
    red[c] = dv * dv;
    __syncthreads();
    for (int off = 128; off > 0; off >>= 1) {
        if (c < off) red[c] += red[c + off];
        __syncthreads();
    }
    float var = red[0] * (1.f / Cn);
    float rs = rsqrtf(var + 1e-5f);
    float xh = dv * rs * ln_g[c] + ln_b[c];
    float gl = 0.5f * xh * (1.f + erff(xh * 0.70710678118654752440f));
    g[(size_t)bt * Cn + c] = gl;
}

// ============================================================
// 6) scatter-add projected windows back into out
// ============================================================
__global__ void scatter_kernel(const float* __restrict__ P, const int* __restrict__ sel,
                               float* __restrict__ out) {
    int n = blockIdx.x;
    int c = threadIdx.x;
    int b = n / NWF;
    int wi = sel[n];
    int wh = wi >> 5, ww = wi & 31;
    const float* src = P + (size_t)n * WINSZ * Cn + c;
    float* dst = out + (((size_t)b * Cn + c) * Hn + wh * WSZ) * Wn + ww * WSZ;
    #pragma unroll
    for (int p = 0; p < WINSZ; p++) {
        dst[(p >> 3) * Wn + (p & 7)] += src[p * Cn];
    }
}

// ============================================================
// launch
// ============================================================
extern "C" void kernel_launch(void* const* d_in, const int* in_sizes, int n_in,
                              void* d_out, int out_size) {
    const float* feat  = (const float*)d_in[0];
    const float* unc   = (const float*)d_in[1];
    const float* sr_w  = (const float*)d_in[2];
    const float* sr_b  = (const float*)d_in[3];
    const float* ln_g  = (const float*)d_in[4];
    const float* ln_b  = (const float*)d_in[5];
    const float* wq_l  = (const float*)d_in[6];
    const float* wkv_l = (const float*)d_in[7];
    const float* wq_g  = (const float*)d_in[8];
    const float* wkv_g = (const float*)d_in[9];
    const float* wp    = (const float*)d_in[10];
    const float* bp    = (const float*)d_in[11];
    float* out = (float*)d_out;

    float *wf, *q, *kv, *g;
    int* sel;
    cudaGetSymbolAddress((void**)&wf,  d_wf);
    cudaGetSymbolAddress((void**)&q,   d_q);
    cudaGetSymbolAddress((void**)&kv,  d_kv);
    cudaGetSymbolAddress((void**)&g,   d_g);
    cudaGetSymbolAddress((void**)&sel, d_sel);

    size_t att_smem = ATT_SMEM_FLOATS * sizeof(float);
    cudaFuncSetAttribute(attn_kernel, cudaFuncAttributeMaxDynamicSharedMemorySize,
                         (int)att_smem);

    cudaMemcpyAsync(out, feat, (size_t)Bn * Cn * Hn * Wn * sizeof(float),
                    cudaMemcpyDeviceToDevice);

    select_kernel<<<Bn, NWIN>>>(unc, sel);
    gather_kernel<<<NSEL, Cn>>>(feat, sel, wf);

    // local branch
    sgemm_kernel<<<dim3(NTOK / 128, Cn / 128), 256>>>(wf, wq_l, q, nullptr, NTOK, Cn, Cn);
    sgemm_kernel<<<dim3(NTOK / 128, 2 * Cn / 128), 256>>>(wf, wkv_l, kv, nullptr, NTOK, 2 * Cn, Cn);
    attn_kernel<<<dim3(NSEL, HEADS), 256, att_smem>>>(q, kv, wf, WINSZ, 0);

    // global branch
    convlngelu_kernel<<<GTOK, Cn>>>(feat, sr_w, sr_b, ln_g, ln_b, g);
    sgemm_kernel<<<dim3(GTOK / 128, 2 * Cn / 128), 256>>>(g, wkv_g, kv, nullptr, GTOK, 2 * Cn, Cn);

    sgemm_kernel<<<dim3(NTOK / 128, Cn / 128), 256>>>(wf, wq_g, q, nullptr, NTOK, Cn, Cn);
    attn_kernel<<<dim3(NSEL, HEADS), 256, att_smem>>>(q, kv, wf, HW1, 1);

    // projection + scatter
    sgemm_kernel<<<dim3(NTOK / 128, Cn / 128), 256>>>(wf, wp, q, bp, NTOK, Cn, Cn);
    scatter_kernel<<<NSEL, Cn>>>(q, sel, out);
}

// round 5
// speedup vs baseline: 2.1236x; 2.0562x over previous
#include <cuda_runtime.h>
#include <cuda_bf16.h>
#include <math.h>
#include <stdint.h>

// ---------------- problem constants ----------------
#define Bn      2
#define Cn      256
#define Hn      256
#define Wn      256
#define HEADS   4
#define CH      64
#define WSZ     8
#define NH      32
#define NWIN    1024
#define WINSZ   64
#define NWF     307
#define NSEL    614
#define SRn     8
#define H1      32
#define HW1     1024
#define NTOK    (NSEL*WINSZ)   // 39296
#define GTOK    (Bn*HW1)       // 2048
#define SCALE   0.125f
#define GK      256

// ---------------- scratch ----------------
__device__ float d_wf[NTOK * Cn];
__device__ float d_q [NTOK * Cn];
__device__ float d_kv[NTOK * 2 * Cn];
__device__ float d_g [GTOK * Cn];
__device__ int   d_sel[NSEL];
__device__ float d_wtql [Cn * Cn];
__device__ float d_wtkvl[2 * Cn * Cn];
__device__ float d_wtqg [Cn * Cn];
__device__ float d_wtkvg[2 * Cn * Cn];
__device__ float d_wtp  [Cn * Cn];

// ---------------- mma helpers ----------------
__device__ __forceinline__ uint32_t f2tf(float x) {
    uint32_t r;
    asm("cvt.rna.tf32.f32 %0, %1;" : "=r"(r) : "f"(x));
    return r;
}
__device__ __forceinline__ void mma_tf32(float d[4], const uint32_t a[4], const uint32_t b[2]) {
    asm volatile(
        "mma.sync.aligned.m16n8k8.row.col.f32.tf32.tf32.f32 "
        "{%0,%1,%2,%3}, {%4,%5,%6,%7}, {%8,%9}, {%0,%1,%2,%3};"
        : "+f"(d[0]), "+f"(d[1]), "+f"(d[2]), "+f"(d[3])
        : "r"(a[0]), "r"(a[1]), "r"(a[2]), "r"(a[3]), "r"(b[0]), "r"(b[1]));
}

// ============================================================
// 0) weight transpose WT[n][k] = W[k][n]
// ============================================================
__global__ void transpose_kernel(const float* __restrict__ W, float* __restrict__ WT, int N) {
    __shared__ float t[32][33];
    int kx = blockIdx.x * 32, nx = blockIdx.y * 32;
    for (int r = threadIdx.y; r < 32; r += 8)
        t[r][threadIdx.x] = W[(size_t)(kx + r) * N + nx + threadIdx.x];
    __syncthreads();
    for (int r = threadIdx.y; r < 32; r += 8)
        WT[(size_t)(nx + r) * GK + kx + threadIdx.x] = t[threadIdx.x][r];
}

// ============================================================
// 1) top-k window selection
// ============================================================
__global__ void select_kernel(const float* __restrict__ unc, int* __restrict__ sel) {
    __shared__ float sc[NWIN];
    int b  = blockIdx.x;
    int wi = threadIdx.x;
    int wh = wi >> 5, ww = wi & 31;
    const float* u = unc + ((size_t)b * Hn + wh * WSZ) * Wn + ww * WSZ;
    float s = 0.f;
    #pragma unroll
    for (int i = 0; i < WSZ; i++)
        #pragma unroll
        for (int j = 0; j < WSZ; j++)
            s += u[i * Wn + j];
    sc[wi] = s;
    __syncthreads();
    int rank = 0;
    for (int j = 0; j < NWIN; j++) {
        float sj = sc[j];
        rank += (sj > s) || (sj == s && j < wi);
    }
    if (rank < NWF) sel[b * NWF + rank] = wi;
}

// ============================================================
// 2) gather selected windows
// ============================================================
__global__ void gather_kernel(const float* __restrict__ feat, const int* __restrict__ sel,
                              float* __restrict__ wf) {
    int n = blockIdx.x;
    int c = threadIdx.x;
    int b = n / NWF;
    int wi = sel[n];
    int wh = wi >> 5, ww = wi & 31;
    const float* src = feat + (((size_t)b * Cn + c) * Hn + wh * WSZ) * Wn + ww * WSZ;
    float* dst = wf + (size_t)n * WINSZ * Cn + c;
    #pragma unroll
    for (int p = 0; p < WINSZ; p++)
        dst[p * Cn] = src[(p >> 3) * Wn + (p & 7)];
}

// ============================================================
// 3) tf32 mma.sync GEMM:  C[m0:+128, n0:+128] = A[128,256] @ WT[128,256]^T
//    8 warps = 2m x 4n; warp = 64x32 = 4x4 m16n8k8 fragments
//    As[m][k], Bs[n][k] stride 36 -> conflict-free fragment LDS
// ============================================================
__global__ __launch_bounds__(256)
void mma_gemm_kernel(const float* __restrict__ A, const float* __restrict__ WT,
                     float* __restrict__ C, const float* __restrict__ bias, int ldc) {
    __shared__ uint32_t As[128][36];
    __shared__ uint32_t Bs[128][36];

    int tid = threadIdx.x;
    int lane = tid & 31, wid = tid >> 5;
    int g = lane >> 2, t = lane & 3;
    int wm = wid & 1, wn = wid >> 1;
    int m0 = blockIdx.x * 128, n0 = blockIdx.y * 128;

    int lrow = tid >> 1;            // 0..127
    int lkq  = (tid & 1) * 16;      // 0 / 16

    float acc[4][4][4] = {};

    for (int kc = 0; kc < GK; kc += 32) {
        const float* ap = A  + (size_t)(m0 + lrow) * GK + kc + lkq;
        const float* bp = WT + (size_t)(n0 + lrow) * GK + kc + lkq;
        #pragma unroll
        for (int qd = 0; qd < 4; qd++) {
            float4 va = *(const float4*)(ap + qd * 4);
            float4 vb = *(const float4*)(bp + qd * 4);
            int c0 = lkq + qd * 4;
            As[lrow][c0 + 0] = f2tf(va.x);
            As[lrow][c0 + 1] = f2tf(va.y);
            As[lrow][c0 + 2] = f2tf(va.z);
            As[lrow][c0 + 3] = f2tf(va.w);
            Bs[lrow][c0 + 0] = f2tf(vb.x);
            Bs[lrow][c0 + 1] = f2tf(vb.y);
            Bs[lrow][c0 + 2] = f2tf(vb.z);
            Bs[lrow][c0 + 3] = f2tf(vb.w);
        }
        __syncthreads();

        #pragma unroll
        for (int ks = 0; ks < 4; ks++) {
            uint32_t af[4][4];
            #pragma unroll
            for (int mf = 0; mf < 4; mf++) {
                int rb = wm * 64 + mf * 16;
                af[mf][0] = As[rb + g    ][ks * 8 + t];
                af[mf][1] = As[rb + g + 8][ks * 8 + t];
                af[mf][2] = As[rb + g    ][ks * 8 + t + 4];
                af[mf][3] = As[rb + g + 8][ks * 8 + t + 4];
            }
            #pragma unroll
            for (int nf = 0; nf < 4; nf++) {
                int nb = wn * 32 + nf * 8;
                uint32_t bf[2];
                bf[0] = Bs[nb + g][ks * 8 + t];
                bf[1] = Bs[nb + g][ks * 8 + t + 4];
                #pragma unroll
                for (int mf = 0; mf < 4; mf++)
                    mma_tf32(acc[mf][nf], af[mf], bf);
            }
        }
        __syncthreads();
    }

    #pragma unroll
    for (int mf = 0; mf < 4; mf++) {
        int r0 = m0 + wm * 64 + mf * 16 + g;
        #pragma unroll
        for (int nf = 0; nf < 4; nf++) {
            int cc = n0 + wn * 32 + nf * 8 + 2 * t;
            float b0 = 0.f, b1 = 0.f;
            if (bias) { b0 = __ldg(&bias[cc]); b1 = __ldg(&bias[cc + 1]); }
            float2 v0 = { acc[mf][nf][0] + b0, acc[mf][nf][1] + b1 };
            float2 v1 = { acc[mf][nf][2] + b0, acc[mf][nf][3] + b1 };
            *(float2*)(C + (size_t)r0 * ldc + cc)       = v0;
            *(float2*)(C + (size_t)(r0 + 8) * ldc + cc) = v1;
        }
    }
}

// ============================================================
// 4) fused flash attention with tf32 mma.sync
//    block = (window, head), 128 threads = 4 warps x 16 query rows
// ============================================================
#define AS_STR 68
#define ATT_SMEM_BYTES (3 * 64 * AS_STR * 4)   // Ks, Vs, Ps

__global__ __launch_bounds__(128)
void attn_kernel(const float* __restrict__ Q, const float* __restrict__ KV,
                 float* __restrict__ wfacc, int nchunks, int gmode) {
    extern __shared__ uint32_t smu[];
    uint32_t* Ks = smu;                    // [64][68] tf32 bits, [key][ch]
    uint32_t* Vs = Ks + 64 * AS_STR;       // [64][68] tf32 bits, [key][ch]
    uint32_t* Ps = Vs + 64 * AS_STR;       // [64][68] tf32 bits, [qrow][key]

    int n = blockIdx.x, h = blockIdx.y;
    int tid = threadIdx.x;
    int lane = tid & 31, w = tid >> 5;
    int g = lane >> 2, t = lane & 3;
    int qtok0 = n * WINSZ;
    int kbase = gmode ? (n / NWF) * HW1 : n * WINSZ;
    int qrow0 = w * 16;

    // Q fragments in registers (scale + tf32 folded), invariant across chunks
    uint32_t qf[8][4];
    {
        const float* qb = Q + (size_t)(qtok0 + qrow0) * Cn + h * CH;
        #pragma unroll
        for (int ks = 0; ks < 8; ks++) {
            qf[ks][0] = f2tf(qb[(size_t)(g    ) * Cn + ks * 8 + t    ] * SCALE);
            qf[ks][1] = f2tf(qb[(size_t)(g + 8) * Cn + ks * 8 + t    ] * SCALE);
            qf[ks][2] = f2tf(qb[(size_t)(g    ) * Cn + ks * 8 + t + 4] * SCALE);
            qf[ks][3] = f2tf(qb[(size_t)(g + 8) * Cn + ks * 8 + t + 4] * SCALE);
        }
    }

    float of[8][4] = {};
    float rm0 = -1e30f, rm1 = -1e30f, rl0 = 0.f, rl1 = 0.f;

    for (int chk = 0; chk < nchunks; chk++) {
        __syncthreads();
        // cooperative K/V load + tf32 convert
        for (int i = tid; i < 1024; i += 128) {
            int tok = i >> 4, c4 = (i & 15) << 2;
            const float* base = KV + (size_t)(kbase + chk * 64 + tok) * (2 * Cn) + h * CH;
            float4 kv4 = *(const float4*)(base + c4);
            float4 vv4 = *(const float4*)(base + Cn + c4);
            uint32_t* kd = Ks + tok * AS_STR + c4;
            uint32_t* vd = Vs + tok * AS_STR + c4;
            kd[0] = f2tf(kv4.x); kd[1] = f2tf(kv4.y); kd[2] = f2tf(kv4.z); kd[3] = f2tf(kv4.w);
            vd[0] = f2tf(vv4.x); vd[1] = f2tf(vv4.y); vd[2] = f2tf(vv4.z); vd[3] = f2tf(vv4.w);
        }
        __syncthreads();

        // S = (Q*scale) @ K^T : warp computes 16x64
        float ss[8][4] = {};
        #pragma unroll
        for (int nf = 0; nf < 8; nf++) {
            #pragma unroll
            for (int ks = 0; ks < 8; ks++) {
                uint32_t bf[2];
                bf[0] = Ks[(nf * 8 + g) * AS_STR + ks * 8 + t];
                bf[1] = Ks[(nf * 8 + g) * AS_STR + ks * 8 + t + 4];
                mma_tf32(ss[nf], qf[ks], bf);
            }
        }

        // online softmax: rows g (c0,c1) and g+8 (c2,c3); groups of 4 lanes
        float cm0 = -1e30f, cm1 = -1e30f;
        #pragma unroll
        for (int nf = 0; nf < 8; nf++) {
            cm0 = fmaxf(cm0, fmaxf(ss[nf][0], ss[nf][1]));
            cm1 = fmaxf(cm1, fmaxf(ss[nf][2], ss[nf][3]));
        }
        cm0 = fmaxf(cm0, __shfl_xor_sync(0xffffffffu, cm0, 1));
        cm0 = fmaxf(cm0, __shfl_xor_sync(0xffffffffu, cm0, 2));
        cm1 = fmaxf(cm1, __shfl_xor_sync(0xffffffffu, cm1, 1));
        cm1 = fmaxf(cm1, __shfl_xor_sync(0xffffffffu, cm1, 2));
        float nm0 = fmaxf(rm0, cm0), nm1 = fmaxf(rm1, cm1);
        float scl0 = __expf(rm0 - nm0), scl1 = __expf(rm1 - nm1);
        float sum0 = 0.f, sum1 = 0.f;
        #pragma unroll
        for (int nf = 0; nf < 8; nf++) {
            ss[nf][0] = __expf(ss[nf][0] - nm0);
            ss[nf][1] = __expf(ss[nf][1] - nm0);
            ss[nf][2] = __expf(ss[nf][2] - nm1);
            ss[nf][3] = __expf(ss[nf][3] - nm1);
            sum0 += ss[nf][0] + ss[nf][1];
            sum1 += ss[nf][2] + ss[nf][3];
        }
        sum0 += __shfl_xor_sync(0xffffffffu, sum0, 1);
        sum0 += __shfl_xor_sync(0xffffffffu, sum0, 2);
        sum1 += __shfl_xor_sync(0xffffffffu, sum1, 1);
        sum1 += __shfl_xor_sync(0xffffffffu, sum1, 2);
        rl0 = rl0 * scl0 + sum0;  rm0 = nm0;
        rl1 = rl1 * scl1 + sum1;  rm1 = nm1;
        #pragma unroll
        for (int nf = 0; nf < 8; nf++) {
            of[nf][0] *= scl0; of[nf][1] *= scl0;
            of[nf][2] *= scl1; of[nf][3] *= scl1;
        }

        // P -> warp-private smem (re-fragment for PV)
        #pragma unroll
        for (int nf = 0; nf < 8; nf++) {
            int pc = nf * 8 + 2 * t;
            uint32_t* p0 = Ps + (qrow0 + g) * AS_STR + pc;
            uint32_t* p1 = Ps + (qrow0 + g + 8) * AS_STR + pc;
            p0[0] = f2tf(ss[nf][0]); p0[1] = f2tf(ss[nf][1]);
            p1[0] = f2tf(ss[nf][2]); p1[1] = f2tf(ss[nf][3]);
        }
        __syncwarp();

        // O += P @ V
        #pragma unroll
        for (int ks2 = 0; ks2 < 8; ks2++) {
            uint32_t pa[4];
            pa[0] = Ps[(qrow0 + g    ) * AS_STR + ks2 * 8 + t];
            pa[1] = Ps[(qrow0 + g + 8) * AS_STR + ks2 * 8 + t];
            pa[2] = Ps[(qrow0 + g    ) * AS_STR + ks2 * 8 + t + 4];
            pa[3] = Ps[(qrow0 + g + 8) * AS_STR + ks2 * 8 + t + 4];
            #pragma unroll
            for (int nf2 = 0; nf2 < 8; nf2++) {
                uint32_t bf[2];
                bf[0] = Vs[(ks2 * 8 + t    ) * AS_STR + nf2 * 8 + g];
                bf[1] = Vs[(ks2 * 8 + t + 4) * AS_STR + nf2 * 8 + g];
                mma_tf32(of[nf2], pa, bf);
            }
        }
        __syncwarp();
    }

    // normalize + residual accumulate
    float inv0 = 1.f / rl0, inv1 = 1.f / rl1;
    #pragma unroll
    for (int nf = 0; nf < 8; nf++) {
        float* p0 = wfacc + (size_t)(qtok0 + qrow0 + g) * Cn + h * CH + nf * 8 + 2 * t;
        float* p1 = wfacc + (size_t)(qtok0 + qrow0 + g + 8) * Cn + h * CH + nf * 8 + 2 * t;
        float2 o0 = *(float2*)p0;
        float2 o1 = *(float2*)p1;
        o0.x += of[nf][0] * inv0; o0.y += of[nf][1] * inv0;
        o1.x += of[nf][2] * inv1; o1.y += of[nf][3] * inv1;
        *(float2*)p0 = o0;
        *(float2*)p1 = o1;
    }
}

// ============================================================
// 5) global branch: depthwise conv -> LN -> exact GELU
// ============================================================
__global__ void convlngelu_kernel(const float* __restrict__ feat,
                                  const float* __restrict__ sr_w,
                                  const float* __restrict__ sr_b,
                                  const float* __restrict__ ln_g,
                                  const float* __restrict__ ln_b,
                                  float* __restrict__ g) {
    __shared__ float red[Cn];
    int bt = blockIdx.x;
    int b = bt >> 10, t = bt & 1023;
    int y1 = t >> 5, x1 = t & 31;
    int c = threadIdx.x;

    const float* src = feat + (((size_t)b * Cn + c) * Hn + y1 * SRn) * Wn + x1 * SRn;
    const float* w = sr_w + c * (SRn * SRn);
    float acc = sr_b[c];
    #pragma unroll
    for (int i = 0; i < SRn; i++)
        #pragma unroll
        for (int j = 0; j < SRn; j++)
            acc += src[i * Wn + j] * w[i * SRn + j];

    red[c] = acc;
    __syncthreads();
    for (int off = 128; off > 0; off >>= 1) {
        if (c < off) red[c] += red[c + off];
        __syncthreads();
    }
    float mu = red[0] * (1.f / Cn);
    __syncthreads();
    float dv = acc - mu;
    red[c] = dv * dv;
    __syncthreads();
    for (int off = 128; off > 0; off >>= 1) {
        if (c < off) red[c] += red[c + off];
        __syncthreads();
    }
    float var = red[0] * (1.f / Cn);
    float rs = rsqrtf(var + 1e-5f);
    float xh = dv * rs * ln_g[c] + ln_b[c];
    float gl = 0.5f * xh * (1.f + erff(xh * 0.70710678118654752440f));
    g[(size_t)bt * Cn + c] = gl;
}

// ============================================================
// 6) scatter-add projected windows back into out
// ============================================================
__global__ void scatter_kernel(const float* __restrict__ P, const int* __restrict__ sel,
                               float* __restrict__ out) {
    int n = blockIdx.x;
    int c = threadIdx.x;
    int b = n / NWF;
    int wi = sel[n];
    int wh = wi >> 5, ww = wi & 31;
    const float* src = P + (size_t)n * WINSZ * Cn + c;
    float* dst = out + (((size_t)b * Cn + c) * Hn + wh * WSZ) * Wn + ww * WSZ;
    #pragma unroll
    for (int p = 0; p < WINSZ; p++)
        dst[(p >> 3) * Wn + (p & 7)] += src[p * Cn];
}

// ============================================================
// launch
// ============================================================
extern "C" void kernel_launch(void* const* d_in, const int* in_sizes, int n_in,
                              void* d_out, int out_size) {
    const float* feat  = (const float*)d_in[0];
    const float* unc   = (const float*)d_in[1];
    const float* sr_w  = (const float*)d_in[2];
    const float* sr_b  = (const float*)d_in[3];
    const float* ln_g  = (const float*)d_in[4];
    const float* ln_b  = (const float*)d_in[5];
    const float* wq_l  = (const float*)d_in[6];
    const float* wkv_l = (const float*)d_in[7];
    const float* wq_g  = (const float*)d_in[8];
    const float* wkv_g = (const float*)d_in[9];
    const float* wp    = (const float*)d_in[10];
    const float* bp    = (const float*)d_in[11];
    float* out = (float*)d_out;

    float *wf, *q, *kv, *g;
    float *wtql, *wtkvl, *wtqg, *wtkvg, *wtp;
    int* sel;
    cudaGetSymbolAddress((void**)&wf,    d_wf);
    cudaGetSymbolAddress((void**)&q,     d_q);
    cudaGetSymbolAddress((void**)&kv,    d_kv);
    cudaGetSymbolAddress((void**)&g,     d_g);
    cudaGetSymbolAddress((void**)&sel,   d_sel);
    cudaGetSymbolAddress((void**)&wtql,  d_wtql);
    cudaGetSymbolAddress((void**)&wtkvl, d_wtkvl);
    cudaGetSymbolAddress((void**)&wtqg,  d_wtqg);
    cudaGetSymbolAddress((void**)&wtkvg, d_wtkvg);
    cudaGetSymbolAddress((void**)&wtp,   d_wtp);

    cudaFuncSetAttribute(attn_kernel, cudaFuncAttributeMaxDynamicSharedMemorySize,
                         ATT_SMEM_BYTES);

    cudaMemcpyAsync(out, feat, (size_t)Bn * Cn * Hn * Wn * sizeof(float),
                    cudaMemcpyDeviceToDevice);

    // weight transposes
    dim3 tb(32, 8);
    transpose_kernel<<<dim3(8, 8),  tb>>>(wq_l,  wtql,  Cn);
    transpose_kernel<<<dim3(8, 16), tb>>>(wkv_l, wtkvl, 2 * Cn);
    transpose_kernel<<<dim3(8, 8),  tb>>>(wq_g,  wtqg,  Cn);
    transpose_kernel<<<dim3(8, 16), tb>>>(wkv_g, wtkvg, 2 * Cn);
    transpose_kernel<<<dim3(8, 8),  tb>>>(wp,    wtp,   Cn);

    select_kernel<<<Bn, NWIN>>>(unc, sel);
    gather_kernel<<<NSEL, Cn>>>(feat, sel, wf);

    // local branch (tensor-core tf32 GEMMs + attention)
    mma_gemm_kernel<<<dim3(NTOK / 128, 2), 256>>>(wf, wtql, q, nullptr, Cn);
    mma_gemm_kernel<<<dim3(NTOK / 128, 4), 256>>>(wf, wtkvl, kv, nullptr, 2 * Cn);
    attn_kernel<<<dim3(NSEL, HEADS), 128, ATT_SMEM_BYTES>>>(q, kv, wf, 1, 0);

    // global branch
    convlngelu_kernel<<<GTOK, Cn>>>(feat, sr_w, sr_b, ln_g, ln_b, g);
    mma_gemm_kernel<<<dim3(GTOK / 128, 4), 256>>>(g, wtkvg, kv, nullptr, 2 * Cn);

    mma_gemm_kernel<<<dim3(NTOK / 128, 2), 256>>>(wf, wtqg, q, nullptr, Cn);
    attn_kernel<<<dim3(NSEL, HEADS), 128, ATT_SMEM_BYTES>>>(q, kv, wf, 16, 1);

    // projection + scatter
    mma_gemm_kernel<<<dim3(NTOK / 128, 2), 256>>>(wf, wtp, q, bp, Cn);
    scatter_kernel<<<NSEL, Cn>>>(q, sel, out);
}